// round 9
// baseline (speedup 1.0000x reference)
#include <cuda_runtime.h>
#include <cuda_bf16.h>
#include <cstdint>

#define BATCH 16
#define LQ    512
#define LC    2048
#define DIM   1024

// ---------------------------------------------------------------------------
// Device scratch (device-side only; symbols NEVER passed from host)
// ---------------------------------------------------------------------------
__device__ float         g_attn  [(size_t)BATCH * LC * LQ];    // fp32 logits
__device__ __nv_bfloat16 g_ctx_hi[(size_t)BATCH * LC * DIM];
__device__ __nv_bfloat16 g_ctx_lo[(size_t)BATCH * LC * DIM];
__device__ __nv_bfloat16 g_q_hi  [(size_t)BATCH * LQ * DIM];
__device__ __nv_bfloat16 g_q_lo  [(size_t)BATCH * LQ * DIM];
__device__ __nv_bfloat16 g_w_hi  [(size_t)BATCH * LC * LQ];    // softmax weights
__device__ __nv_bfloat16 g_w_lo  [(size_t)BATCH * LC * LQ];

// ---------------------------------------------------------------------------
// helpers
// ---------------------------------------------------------------------------
__device__ __forceinline__ uint32_t smem_u32(const void* p) {
    uint32_t a;
    asm("{ .reg .u64 t; cvta.to.shared.u64 t, %1; cvt.u32.u64 %0, t; }" : "=r"(a) : "l"(p));
    return a;
}
__device__ __forceinline__ void cp16(uint32_t dst, const void* src) {
    asm volatile("cp.async.cg.shared.global [%0], [%1], 16;" :: "r"(dst), "l"(src));
}
__device__ __forceinline__ void cp_commit() { asm volatile("cp.async.commit_group;"); }
template <int N>
__device__ __forceinline__ void cp_wait() { asm volatile("cp.async.wait_group %0;" :: "n"(N)); }

__device__ __forceinline__ void ldm4(uint32_t a, uint32_t& r0, uint32_t& r1,
                                     uint32_t& r2, uint32_t& r3) {
    asm volatile("ldmatrix.sync.aligned.m8n8.x4.shared.b16 {%0,%1,%2,%3}, [%4];"
                 : "=r"(r0), "=r"(r1), "=r"(r2), "=r"(r3) : "r"(a));
}
__device__ __forceinline__ void ldm4t(uint32_t a, uint32_t& r0, uint32_t& r1,
                                      uint32_t& r2, uint32_t& r3) {
    asm volatile("ldmatrix.sync.aligned.m8n8.x4.trans.shared.b16 {%0,%1,%2,%3}, [%4];"
                 : "=r"(r0), "=r"(r1), "=r"(r2), "=r"(r3) : "r"(a));
}
__device__ __forceinline__ void mma16816(float* c, uint32_t a0, uint32_t a1, uint32_t a2,
                                         uint32_t a3, uint32_t b0, uint32_t b1) {
    asm volatile(
        "mma.sync.aligned.m16n8k16.row.col.f32.bf16.bf16.f32 "
        "{%0,%1,%2,%3}, {%4,%5,%6,%7}, {%8,%9}, {%0,%1,%2,%3};"
        : "+f"(c[0]), "+f"(c[1]), "+f"(c[2]), "+f"(c[3])
        : "r"(a0), "r"(a1), "r"(a2), "r"(a3), "r"(b0), "r"(b1));
}
// split float4 into packed bf16 hi pair-words and lo pair-words
__device__ __forceinline__ void split4(float4 v, uint32_t& h01, uint32_t& h23,
                                       uint32_t& l01, uint32_t& l23) {
    __nv_bfloat16 hx = __float2bfloat16(v.x), hy = __float2bfloat16(v.y);
    __nv_bfloat16 hz = __float2bfloat16(v.z), hw = __float2bfloat16(v.w);
    float lx = v.x - __bfloat162float(hx), ly = v.y - __bfloat162float(hy);
    float lz = v.z - __bfloat162float(hz), lw = v.w - __bfloat162float(hw);
    __nv_bfloat162 H0(hx, hy), H1(hz, hw);
    __nv_bfloat162 L0 = __floats2bfloat162_rn(lx, ly), L1 = __floats2bfloat162_rn(lz, lw);
    h01 = *(uint32_t*)&H0; h23 = *(uint32_t*)&H1;
    l01 = *(uint32_t*)&L0; l23 = *(uint32_t*)&L1;
}

// ---------------------------------------------------------------------------
// Operand split kernels: fp32 -> bf16 hi/lo device scratch (symbols bound here)
// ---------------------------------------------------------------------------
__global__ __launch_bounds__(256)
void ba_split_ctx(const float* __restrict__ src)
{
    const size_t i = (size_t)blockIdx.x * 256 + threadIdx.x;   // float4 index
    float4 v = ((const float4*)src)[i];
    uint32_t h01, h23, l01, l23;
    split4(v, h01, h23, l01, l23);
    ((uint2*)g_ctx_hi)[i] = make_uint2(h01, h23);
    ((uint2*)g_ctx_lo)[i] = make_uint2(l01, l23);
}
__global__ __launch_bounds__(256)
void ba_split_q(const float* __restrict__ src)
{
    const size_t i = (size_t)blockIdx.x * 256 + threadIdx.x;
    float4 v = ((const float4*)src)[i];
    uint32_t h01, h23, l01, l23;
    split4(v, h01, h23, l01, l23);
    ((uint2*)g_q_hi)[i] = make_uint2(h01, h23);
    ((uint2*)g_q_lo)[i] = make_uint2(l01, l23);
}

// ---------------------------------------------------------------------------
// Split-bf16 mma GEMM, pure cp.async 3-stage pipeline (operands pre-split).
// FIRST : logits[c][q] = ctx . q           K=1024 -> g_attn (fp32)
// !FIRST: attn [c][d] = w . q  (B=[k][n])  K=512  -> out right half
//         + fused copy of the matching 128x128 ctx tile into out left half.
// CTA 128x128, BK=16, 8 warps (64x32 warp tile).
// ---------------------------------------------------------------------------
#define AROWB 48                    // 16 bf16 = 32B + 16B pad (conflict-free)
#define BROWB2 272                  // GEMM2 B rows: 256B + 16B pad
#define STAGE1 (4 * 128 * AROWB)                     // 24576
#define STAGE2 (2 * 128 * AROWB + 2 * 16 * BROWB2)   // 20992

template <bool FIRST>
__global__ __launch_bounds__(256)
void ba_mma(const float* __restrict__ actx, float* __restrict__ gout)
{
    constexpr int KT = FIRST ? DIM : LQ;
    constexpr int NT = KT / 16;
    constexpr int OUTSTRIDE = FIRST ? LQ : 2 * DIM;
    constexpr int OUTOFF    = FIRST ? 0  : DIM;
    constexpr int BHALF = FIRST ? (128 * AROWB) : (16 * BROWB2);
    constexpr int STAGE = FIRST ? STAGE1 : STAGE2;
    constexpr int AH = 0, AL = 128 * AROWB, BH = 2 * 128 * AROWB, BL = BH + BHALF;

    extern __shared__ __align__(16) char sm[];
    const uint32_t sb = smem_u32(sm);

    const int tid  = threadIdx.x;
    const int lane = tid & 31;
    const int warp = tid >> 5;
    const int wm   = warp & 1;         // m offset 64*wm
    const int wn   = warp >> 1;        // n offset 32*wn
    const int b  = blockIdx.z;
    const int yT = blockIdx.y;
    const int xT = blockIdx.x;

    // DEVICE-SIDE symbol binding
    const char *Ahg, *Alg, *Bhg, *Blg;
    if (FIRST) {
        size_t ab = ((size_t)b * LC + (size_t)yT * 128) * DIM * 2;
        size_t bb = ((size_t)b * LQ + (size_t)xT * 128) * DIM * 2;
        Ahg = (const char*)g_ctx_hi + ab; Alg = (const char*)g_ctx_lo + ab;
        Bhg = (const char*)g_q_hi + bb;   Blg = (const char*)g_q_lo + bb;
    } else {
        size_t ab = ((size_t)b * LC + (size_t)yT * 128) * LQ * 2;
        size_t bb = ((size_t)b * LQ * DIM + (size_t)xT * 128) * 2;
        Ahg = (const char*)g_w_hi + ab;  Alg = (const char*)g_w_lo + ab;
        Bhg = (const char*)g_q_hi + bb;  Blg = (const char*)g_q_lo + bb;
    }

    // loader coordinates (one 16B chunk per thread per tile-half)
    const int arow = tid >> 1, acol = (tid & 1) * 16;            // A: 128r x 32B
    const int brow = tid >> 4, bcol = (tid & 15) * 16;           // B2: 16r x 256B

    auto load_stage = [&](int slot, int kt) {
        const uint32_t s0 = sb + slot * STAGE;
        const size_t ga = (size_t)arow * (KT * 2) + (size_t)kt * 32 + acol;
        cp16(s0 + AH + arow * AROWB + acol, Ahg + ga);
        cp16(s0 + AL + arow * AROWB + acol, Alg + ga);
        if (FIRST) {
            cp16(s0 + BH + arow * AROWB + acol, Bhg + ga);
            cp16(s0 + BL + arow * AROWB + acol, Blg + ga);
        } else {
            const size_t gb = (size_t)(kt * 16 + brow) * (DIM * 2) + bcol;
            cp16(s0 + BH + brow * BROWB2 + bcol, Bhg + gb);
            cp16(s0 + BL + brow * BROWB2 + bcol, Blg + gb);
        }
        cp_commit();
    };

    float acc[4][4][4];
#pragma unroll
    for (int m = 0; m < 4; m++)
#pragma unroll
        for (int n = 0; n < 4; n++)
#pragma unroll
            for (int j = 0; j < 4; j++) acc[m][n][j] = 0.f;

    load_stage(0, 0);
    load_stage(1, 1);

    const int lrow = lane & 15;
    const int lkb  = lane & 16;         // second 16B chunk (k+8 / n+8)
    constexpr int I1 = FIRST ? 2 : 1;   // ntile0 second b-reg
    constexpr int J0 = FIRST ? 1 : 2;   // ntile1 first b-reg

    for (int kt = 0; kt < NT; kt++) {
        cp_wait<1>();                   // stage kt resident
        __syncthreads();                // all warps done with slot (kt+2)%3
        if (kt + 2 < NT) load_stage((kt + 2) % 3, kt + 2);
        else             cp_commit();   // keep group-count invariant

        const uint32_t s0 = (kt % 3) * STAGE;

        uint32_t ah[4][4], al[4][4];
#pragma unroll
        for (int mt = 0; mt < 4; mt++) {
            uint32_t ra = sb + s0 + AH + (wm * 64 + mt * 16 + lrow) * AROWB + lkb;
            ldm4(ra, ah[mt][0], ah[mt][1], ah[mt][2], ah[mt][3]);
            uint32_t rl = sb + s0 + AL + (wm * 64 + mt * 16 + lrow) * AROWB + lkb;
            ldm4(rl, al[mt][0], al[mt][1], al[mt][2], al[mt][3]);
        }
#pragma unroll
        for (int p = 0; p < 2; p++) {
            uint32_t bh[4], bl[4];
            if (FIRST) {
                uint32_t rb = sb + s0 + BH + (wn * 32 + p * 16 + lrow) * AROWB + lkb;
                ldm4(rb, bh[0], bh[1], bh[2], bh[3]);
                uint32_t rc = sb + s0 + BL + (wn * 32 + p * 16 + lrow) * AROWB + lkb;
                ldm4(rc, bl[0], bl[1], bl[2], bl[3]);
            } else {
                uint32_t rb = sb + s0 + BH + lrow * BROWB2 + (wn * 32 + p * 16) * 2 + lkb;
                ldm4t(rb, bh[0], bh[1], bh[2], bh[3]);
                uint32_t rc = sb + s0 + BL + lrow * BROWB2 + (wn * 32 + p * 16) * 2 + lkb;
                ldm4t(rc, bl[0], bl[1], bl[2], bl[3]);
            }
#pragma unroll
            for (int mt = 0; mt < 4; mt++) {
                mma16816(acc[mt][2 * p],     ah[mt][0], ah[mt][1], ah[mt][2], ah[mt][3], bh[0],  bh[I1]);
                mma16816(acc[mt][2 * p + 1], ah[mt][0], ah[mt][1], ah[mt][2], ah[mt][3], bh[J0], bh[3]);
                mma16816(acc[mt][2 * p],     al[mt][0], al[mt][1], al[mt][2], al[mt][3], bh[0],  bh[I1]);
                mma16816(acc[mt][2 * p + 1], al[mt][0], al[mt][1], al[mt][2], al[mt][3], bh[J0], bh[3]);
                mma16816(acc[mt][2 * p],     ah[mt][0], ah[mt][1], ah[mt][2], ah[mt][3], bl[0],  bl[I1]);
                mma16816(acc[mt][2 * p + 1], ah[mt][0], ah[mt][1], ah[mt][2], ah[mt][3], bl[J0], bl[3]);
            }
        }
    }

    // epilogue (standard m16n8 C layout)
    float* Cg = FIRST ? (float*)g_attn : gout;
    const size_t rbase = (size_t)b * LC + (size_t)yT * 128 + wm * 64 + (lane >> 2);
    const int    cbase = OUTOFF + xT * 128 + wn * 32 + (lane & 3) * 2;
#pragma unroll
    for (int mt = 0; mt < 4; mt++) {
#pragma unroll
        for (int nt = 0; nt < 4; nt++) {
            size_t r0 = (rbase + mt * 16) * OUTSTRIDE + cbase + nt * 8;
            *(float2*)(Cg + r0)                    = make_float2(acc[mt][nt][0], acc[mt][nt][1]);
            *(float2*)(Cg + r0 + 8ull * OUTSTRIDE) = make_float2(acc[mt][nt][2], acc[mt][nt][3]);
        }
    }

    // fused ctx copy into out LEFT half (GEMM2 only)
    if (!FIRST) {
        const float4* csrc = (const float4*)(actx + ((size_t)b * LC + (size_t)yT * 128) * DIM
                                             + (size_t)xT * 128);
        float4* cdst = (float4*)(gout + ((size_t)b * LC + (size_t)yT * 128) * (2 * DIM)
                                 + (size_t)xT * 128);
        const int crow = tid >> 5;
        const int ccol = tid & 31;
#pragma unroll
        for (int it = 0; it < 16; it++) {
            cdst[(size_t)(crow + it * 8) * (2 * DIM / 4) + ccol] =
                csrc[(size_t)(crow + it * 8) * (DIM / 4) + ccol];
        }
    }
}

// ---------------------------------------------------------------------------
// Warp-per-row softmax over 512 logits: fp32 in (g_attn), bf16 hi/lo out (g_w).
// ---------------------------------------------------------------------------
__global__ __launch_bounds__(256)
void ba_softmax(void)
{
    const int wid = threadIdx.x >> 5, lane = threadIdx.x & 31;
    const size_t row = (size_t)blockIdx.x * 8 + wid;
    const float4* p = (const float4*)(g_attn + row * LQ);

    float4 v[4];
    float mx = -1e30f;
#pragma unroll
    for (int i = 0; i < 4; i++) {
        v[i] = p[i * 32 + lane];
        mx = fmaxf(mx, fmaxf(fmaxf(v[i].x, v[i].y), fmaxf(v[i].z, v[i].w)));
    }
#pragma unroll
    for (int o = 16; o > 0; o >>= 1) mx = fmaxf(mx, __shfl_xor_sync(0xFFFFFFFFu, mx, o));

    float sum = 0.f;
#pragma unroll
    for (int i = 0; i < 4; i++) {
        v[i].x = __expf(v[i].x - mx); v[i].y = __expf(v[i].y - mx);
        v[i].z = __expf(v[i].z - mx); v[i].w = __expf(v[i].w - mx);
        sum += (v[i].x + v[i].y) + (v[i].z + v[i].w);
    }
#pragma unroll
    for (int o = 16; o > 0; o >>= 1) sum += __shfl_xor_sync(0xFFFFFFFFu, sum, o);

    const float inv = 1.0f / sum;
    uint2* ph = (uint2*)(g_w_hi + row * LQ);
    uint2* pl = (uint2*)(g_w_lo + row * LQ);
#pragma unroll
    for (int i = 0; i < 4; i++) {
        v[i].x *= inv; v[i].y *= inv; v[i].z *= inv; v[i].w *= inv;
        uint32_t h01, h23, l01, l23;
        split4(v[i], h01, h23, l01, l23);
        ph[i * 32 + lane] = make_uint2(h01, h23);
        pl[i * 32 + lane] = make_uint2(l01, l23);
    }
}

// ---------------------------------------------------------------------------
extern "C" void kernel_launch(void* const* d_in, const int* in_sizes, int n_in,
                              void* d_out, int out_size)
{
    const float* question = (const float*)d_in[0];
    const float* context  = (const float*)d_in[1];
    if (in_sizes[0] > in_sizes[1]) {
        const float* t = question; question = context; context = t;
    }
    float* out = (float*)d_out;

    cudaFuncSetAttribute(ba_mma<true>,  cudaFuncAttributeMaxDynamicSharedMemorySize, 3 * STAGE1);
    cudaFuncSetAttribute(ba_mma<false>, cudaFuncAttributeMaxDynamicSharedMemorySize, 3 * STAGE2);

    // operand splits (device symbols bound inside kernels)
    ba_split_ctx<<<(size_t)BATCH * LC * DIM / 4 / 256, 256>>>(context);
    ba_split_q  <<<(size_t)BATCH * LQ * DIM / 4 / 256, 256>>>(question);

    // logits = ctx @ q^T -> g_attn
    ba_mma<true><<<dim3(LQ / 128, LC / 128, BATCH), 256, 3 * STAGE1>>>(context, nullptr);
    // softmax in place -> bf16 hi/lo weights
    ba_softmax<<<BATCH * LC / 8, 256>>>();
    // attn_out = w @ q -> right half of out, + fused ctx copy -> left half
    ba_mma<false><<<dim3(DIM / 128, LC / 128, BATCH), 256, 3 * STAGE2>>>(context, out);
}